// round 7
// baseline (speedup 1.0000x reference)
#include <cuda_runtime.h>
#include <cstdint>

// Sparse dropout: out_values[i] = mask[i] ? values[i] * (1/KPROB) : 0
// KPROB = 0.5 -> scale = 2.0f
//
// Inputs (harness-marshaled):
//   d_in[0]: indices  int32, 2*NNZ elements
//   d_in[1]: values   float32, NNZ elements
//   d_in[2]: mask     int32 (0/1), NNZ elements
//
// Output (float32): [indices cast to f32 (2*NNZ)] ++ [dropout values (NNZ)]
// (falls back to values-only if out_size < 3*NNZ)

static constexpr float SCALE = 2.0f;  // 1 / KPROB

// Dropout, 2 strided float4+int4 pairs per thread (4 independent 16B loads
// front-batched -> MLP=4), streaming cache hints (single-touch data).
// UNCHANGED from R6 (verified 51.1us @ 6628 GB/s).
__global__ void __launch_bounds__(256)
dropout_vec4x2(const float4* __restrict__ vals,
               const int4* __restrict__ mask4,
               float4* __restrict__ out,
               int half) {
    int i = blockIdx.x * blockDim.x + threadIdx.x;
    if (i < half) {
        float4 v0 = __ldcs(&vals[i]);
        float4 v1 = __ldcs(&vals[i + half]);
        int4   m0 = __ldcs(&mask4[i]);
        int4   m1 = __ldcs(&mask4[i + half]);
        float4 o0, o1;
        o0.x = m0.x ? v0.x * SCALE : 0.0f;
        o0.y = m0.y ? v0.y * SCALE : 0.0f;
        o0.z = m0.z ? v0.z * SCALE : 0.0f;
        o0.w = m0.w ? v0.w * SCALE : 0.0f;
        o1.x = m1.x ? v1.x * SCALE : 0.0f;
        o1.y = m1.y ? v1.y * SCALE : 0.0f;
        o1.z = m1.z ? v1.z * SCALE : 0.0f;
        o1.w = m1.w ? v1.w * SCALE : 0.0f;
        __stcs(&out[i], o0);
        __stcs(&out[i + half], o1);
    }
}

// Scalar dropout tail.
__global__ void __launch_bounds__(256)
dropout_tail(const float* __restrict__ vals,
             const int* __restrict__ mask,
             float* __restrict__ out,
             int start, int n) {
    int i = start + blockIdx.x * blockDim.x + threadIdx.x;
    if (i < n) {
        out[i] = mask[i] ? vals[i] * SCALE : 0.0f;
    }
}

// Index cast, 4 strided int4 -> float4 per thread (4 independent 16B loads
// front-batched -> MLP=4, matching the dropout kernel's proven config).
__global__ void __launch_bounds__(256)
idx_cast_vec4x4(const int4* __restrict__ idx,
                float4* __restrict__ out,
                int quarter) {
    int i = blockIdx.x * blockDim.x + threadIdx.x;
    if (i < quarter) {
        int4 a = __ldcs(&idx[i]);
        int4 b = __ldcs(&idx[i + quarter]);
        int4 c = __ldcs(&idx[i + 2 * quarter]);
        int4 d = __ldcs(&idx[i + 3 * quarter]);
        __stcs(&out[i],               make_float4((float)a.x, (float)a.y, (float)a.z, (float)a.w));
        __stcs(&out[i + quarter],     make_float4((float)b.x, (float)b.y, (float)b.z, (float)b.w));
        __stcs(&out[i + 2 * quarter], make_float4((float)c.x, (float)c.y, (float)c.z, (float)c.w));
        __stcs(&out[i + 3 * quarter], make_float4((float)d.x, (float)d.y, (float)d.z, (float)d.w));
    }
}

__global__ void __launch_bounds__(256)
idx_cast_tail(const int* __restrict__ idx,
              float* __restrict__ out,
              int start, int n) {
    int i = start + blockIdx.x * blockDim.x + threadIdx.x;
    if (i < n) {
        out[i] = (float)idx[i];
    }
}

static inline int blocks_for(int n, int tpb) {
    return (int)(((long long)n + tpb - 1) / tpb);
}

extern "C" void kernel_launch(void* const* d_in, const int* in_sizes, int n_in,
                              void* d_out, int out_size) {
    const int*   indices = (const int*)d_in[0];
    const float* values  = (const float*)d_in[1];
    const int*   mask    = (const int*)d_in[2];

    const int n_idx = in_sizes[0];   // 2 * NNZ
    const int nnz   = in_sizes[1];   // NNZ

    const int TPB = 256;

    float* out_values = (float*)d_out;

    if (out_size >= n_idx + nnz) {
        float* out_idx = (float*)d_out;
        out_values = (float*)d_out + n_idx;

        int n4i = n_idx / 4;         // full vec4 elements
        int quarter = n4i / 4;       // per-thread group count
        if (quarter > 0) {
            idx_cast_vec4x4<<<blocks_for(quarter, TPB), TPB>>>(
                (const int4*)indices, (float4*)out_idx, quarter);
        }
        int donei = quarter * 4 * 4; // elements covered by the vec kernel
        if (donei < n_idx) {
            idx_cast_tail<<<blocks_for(n_idx - donei, TPB), TPB>>>(
                indices, out_idx, donei, n_idx);
        }
    }

    int n4   = nnz / 4;
    int half = n4 / 2;
    if (half > 0) {
        dropout_vec4x2<<<blocks_for(half, TPB), TPB>>>(
            (const float4*)values, (const int4*)mask,
            (float4*)out_values, half);
    }
    int done = half * 2 * 4;
    if (done < nnz) {
        dropout_tail<<<blocks_for(nnz - done, TPB), TPB>>>(
            values, mask, out_values, done, nnz);
    }
}

// round 8
// speedup vs baseline: 1.0297x; 1.0297x over previous
#include <cuda_runtime.h>
#include <cstdint>

// Sparse dropout: out_values[i] = mask[i] ? values[i] * (1/KPROB) : 0
// KPROB = 0.5 -> scale = 2.0f
//
// Inputs (harness-marshaled):
//   d_in[0]: indices  int32, 2*NNZ elements
//   d_in[1]: values   float32, NNZ elements
//   d_in[2]: mask     int32 (0/1), NNZ elements
//
// Output (float32): [indices cast to f32 (2*NNZ)] ++ [dropout values (NNZ)]
// (falls back to values-only if out_size < 3*NNZ)
//
// Single fused kernel: grid is partitioned by blockIdx into an idx-cast
// region and a dropout region so the two DRAM-bound tasks share the chip
// with no inter-kernel ramp-down/ramp-up bubble.

static constexpr float SCALE = 2.0f;  // 1 / KPROB

__global__ void __launch_bounds__(256)
fused_sparse_dropout(const int4* __restrict__ idx,      // indices as int4
                     float4* __restrict__ out_idx,      // f32 indices out
                     int halfi,                         // idx int4-pairs per stride
                     int blocks_i,                      // blocks assigned to idx-cast
                     const float4* __restrict__ vals,
                     const int4* __restrict__ mask4,
                     float4* __restrict__ out_vals,
                     int halfv) {                       // value vec4-pairs per stride
    int b = blockIdx.x;
    if (b < blocks_i) {
        // ---- index cast: 2 strided int4 -> float4 per thread (MLP=2) ----
        int i = b * blockDim.x + threadIdx.x;
        if (i < halfi) {
            int4 a0 = __ldcs(&idx[i]);
            int4 a1 = __ldcs(&idx[i + halfi]);
            __stcs(&out_idx[i],
                   make_float4((float)a0.x, (float)a0.y, (float)a0.z, (float)a0.w));
            __stcs(&out_idx[i + halfi],
                   make_float4((float)a1.x, (float)a1.y, (float)a1.z, (float)a1.w));
        }
    } else {
        // ---- dropout: 2 strided float4+int4 pairs per thread (MLP=4) ----
        int i = (b - blocks_i) * blockDim.x + threadIdx.x;
        if (i < halfv) {
            float4 v0 = __ldcs(&vals[i]);
            float4 v1 = __ldcs(&vals[i + halfv]);
            int4   m0 = __ldcs(&mask4[i]);
            int4   m1 = __ldcs(&mask4[i + halfv]);
            float4 o0, o1;
            o0.x = m0.x ? v0.x * SCALE : 0.0f;
            o0.y = m0.y ? v0.y * SCALE : 0.0f;
            o0.z = m0.z ? v0.z * SCALE : 0.0f;
            o0.w = m0.w ? v0.w * SCALE : 0.0f;
            o1.x = m1.x ? v1.x * SCALE : 0.0f;
            o1.y = m1.y ? v1.y * SCALE : 0.0f;
            o1.z = m1.z ? v1.z * SCALE : 0.0f;
            o1.w = m1.w ? v1.w * SCALE : 0.0f;
            __stcs(&out_vals[i], o0);
            __stcs(&out_vals[i + halfv], o1);
        }
    }
}

// Scalar tails (not expected to trigger: 64M and 32M are divisible by 8).
__global__ void __launch_bounds__(256)
idx_cast_tail(const int* __restrict__ idx, float* __restrict__ out,
              int start, int n) {
    int i = start + blockIdx.x * blockDim.x + threadIdx.x;
    if (i < n) out[i] = (float)idx[i];
}

__global__ void __launch_bounds__(256)
dropout_tail(const float* __restrict__ vals, const int* __restrict__ mask,
             float* __restrict__ out, int start, int n) {
    int i = start + blockIdx.x * blockDim.x + threadIdx.x;
    if (i < n) out[i] = mask[i] ? vals[i] * SCALE : 0.0f;
}

static inline int blocks_for(int n, int tpb) {
    return (int)(((long long)n + tpb - 1) / tpb);
}

extern "C" void kernel_launch(void* const* d_in, const int* in_sizes, int n_in,
                              void* d_out, int out_size) {
    const int*   indices = (const int*)d_in[0];
    const float* values  = (const float*)d_in[1];
    const int*   mask    = (const int*)d_in[2];

    const int n_idx = in_sizes[0];   // 2 * NNZ
    const int nnz   = in_sizes[1];   // NNZ

    const int TPB = 256;

    const bool combined = (out_size >= n_idx + nnz);
    float* out_idx    = (float*)d_out;
    float* out_values = combined ? ((float*)d_out + n_idx) : (float*)d_out;

    // Vectorized coverage
    int halfi = combined ? (n_idx / 4) / 2 : 0;   // int4 pairs for idx-cast
    int halfv = (nnz / 4) / 2;                    // vec4 pairs for dropout

    int blocks_i = halfi > 0 ? blocks_for(halfi, TPB) : 0;
    int blocks_d = halfv > 0 ? blocks_for(halfv, TPB) : 0;

    if (blocks_i + blocks_d > 0) {
        fused_sparse_dropout<<<blocks_i + blocks_d, TPB>>>(
            (const int4*)indices, (float4*)out_idx, halfi, blocks_i,
            (const float4*)values, (const int4*)mask,
            (float4*)out_values, halfv);
    }

    // Tails (cover any elements beyond the vectorized region)
    if (combined) {
        int donei = halfi * 2 * 4;
        if (donei < n_idx) {
            idx_cast_tail<<<blocks_for(n_idx - donei, TPB), TPB>>>(
                indices, out_idx, donei, n_idx);
        }
    }
    int donev = halfv * 2 * 4;
    if (donev < nnz) {
        dropout_tail<<<blocks_for(nnz - donev, TPB), TPB>>>(
            values, mask, out_values, donev, nnz);
    }
}